// round 1
// baseline (speedup 1.0000x reference)
#include <cuda_runtime.h>
#include <cuda_bf16.h>

#define NV   200000
#define KOFF 27
#define CA   64
#define CB   128
#define NBLK 256          // fixed partial-reduction block count (deterministic)
#define EPSF 1e-5f

// ---------------- device scratch (no allocations allowed) ----------------
__device__ float g_h0[(NV + 1) * CA];   // BN1 output (+ zero dummy row)
__device__ float g_h1[(NV + 1) * CB];   // conv1 out, then BN2'd in place (+ zero dummy row)
__device__ int   g_g2[KOFF * NV];       // inverse kernel map: gather index per (k, out-row)
__device__ float g_psum[NBLK * CB];
__device__ float g_psq [NBLK * CB];
__device__ float g_a[CB];               // fused BN scale
__device__ float g_bb[CB];              // fused BN shift

// ---------------- inverse kernel map ----------------
__global__ void k_init_g2() {
    int i = blockIdx.x * blockDim.x + threadIdx.x;
    if (i < KOFF * NV) g_g2[i] = NV;
}

__global__ void k_build_g2(const int* __restrict__ gidx, const int* __restrict__ sidx) {
    int i = blockIdx.x * blockDim.x + threadIdx.x;
    if (i >= KOFF * NV) return;
    int s = sidx[i];
    if (s < NV) {
        int k = i / NV;
        g_g2[k * NV + s] = gidx[i];
    }
}

// ---------------- BN: deterministic two-stage reduction ----------------
template <int C>
__global__ void k_bn_partial(const float* __restrict__ x) {
    // 256 threads/block, NBLK blocks. Channel of every element a thread touches
    // is constant (256 and the stride are multiples of C).
    float s = 0.f, s2 = 0.f;
    const int tid = threadIdx.x;
    const int total = NV * C;
    for (int e = blockIdx.x * 256 + tid; e < total; e += NBLK * 256) {
        float v = x[e];
        s  += v;
        s2 += v * v;
    }
    __shared__ float sh[256];
    sh[tid] = s;
    __syncthreads();
    if (tid < C) {
        float a = sh[tid];
        #pragma unroll
        for (int o = C; o < 256; o += C) a += sh[tid + o];
        g_psum[blockIdx.x * C + tid] = a;
    }
    __syncthreads();
    sh[tid] = s2;
    __syncthreads();
    if (tid < C) {
        float a = sh[tid];
        #pragma unroll
        for (int o = C; o < 256; o += C) a += sh[tid + o];
        g_psq[blockIdx.x * C + tid] = a;
    }
}

template <int C>
__global__ void k_bn_finalize(const float* __restrict__ gamma, const float* __restrict__ beta) {
    int c = threadIdx.x;
    if (c >= C) return;
    float s = 0.f, s2 = 0.f;
    for (int b = 0; b < NBLK; ++b) {
        s  += g_psum[b * C + c];
        s2 += g_psq [b * C + c];
    }
    float mean = s / (float)NV;
    float var  = s2 / (float)NV - mean * mean;
    float rstd = rsqrtf(var + EPSF);
    float a = rstd * gamma[c];
    g_a[c]  = a;
    g_bb[c] = beta[c] - mean * a;
}

template <int C>
__global__ void k_bn_apply(const float* __restrict__ x, float* __restrict__ y) {
    // processes (NV+1) rows; rows >= NV are forced to zero (dummy gather row)
    int i = blockIdx.x * blockDim.x + threadIdx.x;       // float4 index
    const int n4 = (NV + 1) * C / 4;
    if (i >= n4) return;
    int e   = i * 4;
    int row = e / C;
    int c   = e % C;                                     // multiple of 4
    float4 o;
    if (row >= NV) {
        o = make_float4(0.f, 0.f, 0.f, 0.f);
    } else {
        float4 v = ((const float4*)x)[i];
        o.x = v.x * g_a[c + 0] + g_bb[c + 0];
        o.y = v.y * g_a[c + 1] + g_bb[c + 1];
        o.z = v.z * g_a[c + 2] + g_bb[c + 2];
        o.w = v.w * g_a[c + 3] + g_bb[c + 3];
    }
    ((float4*)y)[i] = o;
}

// ---------------- gather-GEMM conv ----------------
// Block: 256 threads, computes a [64 x 128] output tile.
// out[i] = sum_k src[g2[k][i]] @ w[k]   (+ feats[i] @ w_nin if ADD_SKIP)
template <int CIN, bool ADD_SKIP>
__global__ void __launch_bounds__(256)
k_conv(const float* __restrict__ src, const float* __restrict__ w,
       const float* __restrict__ feats, const float* __restrict__ wnin,
       float* __restrict__ dst) {
    extern __shared__ float sm[];
    int*   sG = (int*)sm;                    // [KOFF*64] gather indices for this tile
    float* As = sm + KOFF * 64;              // [64][CIN]  gathered rows (row-major)
    float* Bs = As + 64 * CIN;               // [CIN][128] weights

    const int tid  = threadIdx.x;
    const int ct   = tid & 31;               // column group: cols [4*ct, 4*ct+3]
    const int rt   = tid >> 5;               // row group: rows [8*rt, 8*rt+7]
    const int row0 = blockIdx.x * 64;

    for (int i = tid; i < KOFF * 64; i += 256) {
        int k = i >> 6, r = i & 63;
        sG[i] = g_g2[k * NV + row0 + r];
    }
    __syncthreads();

    float acc[8][4];
    #pragma unroll
    for (int j = 0; j < 8; ++j)
        #pragma unroll
        for (int c = 0; c < 4; ++c) acc[j][c] = 0.f;

    const int C4 = CIN / 4;

    for (int k = 0; k < KOFF; ++k) {
        // gather 64 source rows into As (coalesced float4 per row)
        for (int i = tid; i < 64 * C4; i += 256) {
            int r = i / C4, c = i - r * C4;
            int g = sG[k * 64 + r];
            ((float4*)As)[i] = ((const float4*)src)[g * C4 + c];
        }
        // stream w[k] into Bs
        const float4* wk = (const float4*)(w + k * CIN * 128);
        for (int i = tid; i < CIN * 32; i += 256) ((float4*)Bs)[i] = wk[i];
        __syncthreads();

        #pragma unroll 8
        for (int kk = 0; kk < CIN; kk += 4) {
            float4 b0 = ((const float4*)Bs)[(kk + 0) * 32 + ct];
            float4 b1 = ((const float4*)Bs)[(kk + 1) * 32 + ct];
            float4 b2 = ((const float4*)Bs)[(kk + 2) * 32 + ct];
            float4 b3 = ((const float4*)Bs)[(kk + 3) * 32 + ct];
            #pragma unroll
            for (int j = 0; j < 8; ++j) {
                float4 a = ((const float4*)As)[(rt * 8 + j) * C4 + (kk >> 2)];
                acc[j][0] += a.x * b0.x; acc[j][0] += a.y * b1.x; acc[j][0] += a.z * b2.x; acc[j][0] += a.w * b3.x;
                acc[j][1] += a.x * b0.y; acc[j][1] += a.y * b1.y; acc[j][1] += a.z * b2.y; acc[j][1] += a.w * b3.y;
                acc[j][2] += a.x * b0.z; acc[j][2] += a.y * b1.z; acc[j][2] += a.z * b2.z; acc[j][2] += a.w * b3.z;
                acc[j][3] += a.x * b0.w; acc[j][3] += a.y * b1.w; acc[j][3] += a.z * b2.w; acc[j][3] += a.w * b3.w;
            }
        }
        __syncthreads();
    }

    if (ADD_SKIP) {
        // skip: feats[row] @ w_nin  (Cin = 64, identity gather, contiguous rows)
        for (int i = tid; i < 64 * 16; i += 256) {
            int r = i >> 4, c = i & 15;
            ((float4*)As)[i] = ((const float4*)feats)[(row0 + r) * 16 + c];
        }
        for (int i = tid; i < 64 * 32; i += 256) ((float4*)Bs)[i] = ((const float4*)wnin)[i];
        __syncthreads();

        #pragma unroll 8
        for (int kk = 0; kk < 64; kk += 4) {
            float4 b0 = ((const float4*)Bs)[(kk + 0) * 32 + ct];
            float4 b1 = ((const float4*)Bs)[(kk + 1) * 32 + ct];
            float4 b2 = ((const float4*)Bs)[(kk + 2) * 32 + ct];
            float4 b3 = ((const float4*)Bs)[(kk + 3) * 32 + ct];
            #pragma unroll
            for (int j = 0; j < 8; ++j) {
                float4 a = ((const float4*)As)[(rt * 8 + j) * 16 + (kk >> 2)];
                acc[j][0] += a.x * b0.x; acc[j][0] += a.y * b1.x; acc[j][0] += a.z * b2.x; acc[j][0] += a.w * b3.x;
                acc[j][1] += a.x * b0.y; acc[j][1] += a.y * b1.y; acc[j][1] += a.z * b2.y; acc[j][1] += a.w * b3.y;
                acc[j][2] += a.x * b0.z; acc[j][2] += a.y * b1.z; acc[j][2] += a.z * b2.z; acc[j][2] += a.w * b3.z;
                acc[j][3] += a.x * b0.w; acc[j][3] += a.y * b1.w; acc[j][3] += a.z * b2.w; acc[j][3] += a.w * b3.w;
            }
        }
        __syncthreads();
    }

    #pragma unroll
    for (int j = 0; j < 8; ++j) {
        int r = row0 + rt * 8 + j;
        ((float4*)dst)[r * 32 + ct] = make_float4(acc[j][0], acc[j][1], acc[j][2], acc[j][3]);
    }
}

// ---------------- launch ----------------
extern "C" void kernel_launch(void* const* d_in, const int* in_sizes, int n_in,
                              void* d_out, int out_size) {
    const float* feats     = (const float*)d_in[0];   // [N,64]
    const float* w1        = (const float*)d_in[1];   // [27,64,128]
    const float* w2        = (const float*)d_in[2];   // [27,128,128]
    const float* w_nin     = (const float*)d_in[3];   // [64,128]
    const float* bn1_gamma = (const float*)d_in[4];
    const float* bn1_beta  = (const float*)d_in[5];
    const float* bn2_gamma = (const float*)d_in[6];
    const float* bn2_beta  = (const float*)d_in[7];
    const int*   gidx      = (const int*)d_in[8];     // [27,N]
    const int*   sidx      = (const int*)d_in[9];     // [27,N]
    float*       out       = (float*)d_out;           // [N,128]

    const int smem1 = (KOFF * 64) * 4 + (64 * CA) * 4 + (CA * 128) * 4;   // ~56 KB
    const int smem2 = (KOFF * 64) * 4 + (64 * CB) * 4 + (CB * 128) * 4;   // ~105 KB
    cudaFuncSetAttribute(k_conv<CA, false>, cudaFuncAttributeMaxDynamicSharedMemorySize, smem1);
    cudaFuncSetAttribute(k_conv<CB, true >, cudaFuncAttributeMaxDynamicSharedMemorySize, smem2);

    const int mapThreads = KOFF * NV;
    k_init_g2 <<<(mapThreads + 255) / 256, 256>>>();
    k_build_g2<<<(mapThreads + 255) / 256, 256>>>(gidx, sidx);

    // BN1 on feats -> g_h0 (with zero dummy row)
    k_bn_partial<CA> <<<NBLK, 256>>>(feats);
    k_bn_finalize<CA><<<1, CA>>>(bn1_gamma, bn1_beta);
    {
        int n4 = (NV + 1) * CA / 4;
        k_bn_apply<CA><<<(n4 + 255) / 256, 256>>>(feats, g_h0);
    }

    // conv1: g_h0 (+g2) @ w1 -> g_h1 (raw)
    k_conv<CA, false><<<NV / 64, 256, smem1>>>(g_h0, w1, nullptr, nullptr, g_h1);

    // BN2 on g_h1 in place (with zero dummy row)
    k_bn_partial<CB> <<<NBLK, 256>>>(g_h1);
    k_bn_finalize<CB><<<1, CB>>>(bn2_gamma, bn2_beta);
    {
        int n4 = (NV + 1) * CB / 4;
        k_bn_apply<CB><<<(n4 + 255) / 256, 256>>>(g_h1, g_h1);
    }

    // conv2 + fused skip -> out
    k_conv<CB, true><<<NV / 64, 256, smem2>>>(g_h1, w2, feats, w_nin, out);
}

// round 3
// speedup vs baseline: 4.1858x; 4.1858x over previous
#include <cuda_runtime.h>
#include <cuda_bf16.h>
#include <cstdint>

#define NV   200000
#define KOFF 27
#define CA   64
#define CB   128
#define NBLK 256
#define EPSF 1e-5f

// ---------------- device scratch ----------------
__device__ float g_h0 [(NV + 1) * CA];   // BN1(feats), tf32-rounded, zero dummy row
__device__ float g_h1 [NV * CB];         // conv1 raw fp32 output
__device__ float g_h1b[(NV + 1) * CB];   // BN2(h1), tf32-rounded, zero dummy row
__device__ float g_f0 [NV * CA];         // feats tf32-rounded (skip path)
__device__ int   g_g2 [KOFF * NV];       // inverse kernel map
__device__ float g_w1t[KOFF * CB * CA];  // w1 [k][n][c], tf32-rounded
__device__ float g_w2t[KOFF * CB * CB];  // w2 [k][n][c], tf32-rounded
__device__ float g_wnt[CB * CA];         // w_nin [n][c], tf32-rounded
__device__ float g_psum[NBLK * CB];
__device__ float g_psq [NBLK * CB];
__device__ float g_sc[2][CB];
__device__ float g_sh[2][CB];

// ---------------- helpers ----------------
__device__ __forceinline__ uint32_t smem_u32(const void* p) {
    uint32_t a;
    asm("{ .reg .u64 t; cvta.to.shared.u64 t, %1; cvt.u32.u64 %0, t; }" : "=r"(a) : "l"(p));
    return a;
}
__device__ __forceinline__ float tf32r(float x) {
    uint32_t u;
    asm("cvt.rna.tf32.f32 %0, %1;" : "=r"(u) : "f"(x));
    return __uint_as_float(u);
}
__device__ __forceinline__ void cpa16(uint32_t s, const void* g) {
    asm volatile("cp.async.cg.shared.global [%0], [%1], 16;" :: "r"(s), "l"(g));
}
__device__ __forceinline__ void cpa16z(uint32_t s, const void* g, int sz) {
    asm volatile("cp.async.cg.shared.global [%0], [%1], 16, %2;" :: "r"(s), "l"(g), "r"(sz));
}
__device__ __forceinline__ void cpa_commit() {
    asm volatile("cp.async.commit_group;" ::: "memory");
}
__device__ __forceinline__ void cpa_wait1() {
    asm volatile("cp.async.wait_group 1;" ::: "memory");
}
__device__ __forceinline__ void cpa_wait0() {
    asm volatile("cp.async.wait_group 0;" ::: "memory");
}
__device__ __forceinline__ void mma8(float* c, const uint32_t* a, const uint32_t* b) {
    asm volatile(
        "mma.sync.aligned.m16n8k8.row.col.f32.tf32.tf32.f32 "
        "{%0,%1,%2,%3}, {%4,%5,%6,%7}, {%8,%9}, {%0,%1,%2,%3};"
        : "+f"(c[0]), "+f"(c[1]), "+f"(c[2]), "+f"(c[3])
        : "r"(a[0]), "r"(a[1]), "r"(a[2]), "r"(a[3]), "r"(b[0]), "r"(b[1]));
}

// ---------------- inverse kernel map ----------------
__global__ void k_init_g2() {
    int i = blockIdx.x * blockDim.x + threadIdx.x;
    if (i < KOFF * NV) g_g2[i] = NV;
}
__global__ void k_build_g2(const int* __restrict__ gidx, const int* __restrict__ sidx) {
    int i = blockIdx.x * blockDim.x + threadIdx.x;
    if (i >= KOFF * NV) return;
    int s = sidx[i];
    if (s < NV) {
        int k = i / NV;
        g_g2[k * NV + s] = gidx[i];
    }
}

// ---------------- weight transpose w[k][c][n] -> wt[k][n][c] (tf32 rounded) --
__global__ void k_transpose(const float* __restrict__ w, float* __restrict__ wt,
                            int kn, int cin) {
    int i = blockIdx.x * blockDim.x + threadIdx.x;
    int tot = kn * cin * 128;
    if (i >= tot) return;
    int k = i / (cin * 128);
    int rem = i - k * cin * 128;
    int c = rem >> 7, n = rem & 127;
    wt[(k * 128 + n) * cin + c] = tf32r(w[i]);
}

// ---------------- round feats copy ----------------
__global__ void k_round(const float* __restrict__ x, float* __restrict__ y, int tot) {
    int i = blockIdx.x * blockDim.x + threadIdx.x;
    if (i < tot) y[i] = tf32r(x[i]);
}

// ---------------- BN stats (deterministic two-stage) ----------------
template <int C>
__global__ void k_bn_partial(const float* __restrict__ x) {
    const int C4 = C / 4;
    float4 s = make_float4(0.f, 0.f, 0.f, 0.f);
    float4 q = make_float4(0.f, 0.f, 0.f, 0.f);
    const int tot = NV * C4;
    const int tid = threadIdx.x;
    for (int i = blockIdx.x * 256 + tid; i < tot; i += NBLK * 256) {
        float4 v = ((const float4*)x)[i];
        s.x += v.x; s.y += v.y; s.z += v.z; s.w += v.w;
        q.x += v.x * v.x; q.y += v.y * v.y; q.z += v.z * v.z; q.w += v.w * v.w;
    }
    __shared__ float4 sh[256];
    sh[tid] = s;
    __syncthreads();
    if (tid < C4) {
        float4 a = sh[tid];
        for (int o = C4; o < 256; o += C4) {
            float4 b = sh[tid + o];
            a.x += b.x; a.y += b.y; a.z += b.z; a.w += b.w;
        }
        ((float4*)(g_psum + blockIdx.x * C))[tid] = a;
    }
    __syncthreads();
    sh[tid] = q;
    __syncthreads();
    if (tid < C4) {
        float4 a = sh[tid];
        for (int o = C4; o < 256; o += C4) {
            float4 b = sh[tid + o];
            a.x += b.x; a.y += b.y; a.z += b.z; a.w += b.w;
        }
        ((float4*)(g_psq + blockIdx.x * C))[tid] = a;
    }
}

template <int C, int IDX>
__global__ void k_bn_finalize(const float* __restrict__ gamma, const float* __restrict__ beta) {
    const int tid = threadIdx.x;   // blockDim = 4*C
    const int c = tid % C;
    const int qd = tid / C;
    float s = 0.f, s2 = 0.f;
    #pragma unroll 8
    for (int b = qd * (NBLK / 4); b < (qd + 1) * (NBLK / 4); ++b) {
        s  += g_psum[b * C + c];
        s2 += g_psq [b * C + c];
    }
    __shared__ float sha[4 * CB], shb[4 * CB];
    sha[tid] = s; shb[tid] = s2;
    __syncthreads();
    if (qd == 0) {
        s  = sha[c] + sha[C + c] + sha[2 * C + c] + sha[3 * C + c];
        s2 = shb[c] + shb[C + c] + shb[2 * C + c] + shb[3 * C + c];
        float mean = s / (float)NV;
        float var  = s2 / (float)NV - mean * mean;
        float a = rsqrtf(var + EPSF) * gamma[c];
        g_sc[IDX][c] = a;
        g_sh[IDX][c] = beta[c] - mean * a;
    }
}

// ---------------- BN apply + tf32 round, (NV+1) rows with zero dummy --------
template <int C, int IDX>
__global__ void k_bn_apply(const float* __restrict__ x, float* __restrict__ y) {
    int i = blockIdx.x * blockDim.x + threadIdx.x;   // float4 index
    const int n4 = (NV + 1) * C / 4;
    if (i >= n4) return;
    int e = i * 4;
    int row = e / C;
    int c = e % C;
    float4 o;
    if (row >= NV) {
        o = make_float4(0.f, 0.f, 0.f, 0.f);
    } else {
        float4 v = ((const float4*)x)[i];
        o.x = tf32r(v.x * g_sc[IDX][c + 0] + g_sh[IDX][c + 0]);
        o.y = tf32r(v.y * g_sc[IDX][c + 1] + g_sh[IDX][c + 1]);
        o.z = tf32r(v.z * g_sc[IDX][c + 2] + g_sh[IDX][c + 2]);
        o.w = tf32r(v.w * g_sc[IDX][c + 3] + g_sh[IDX][c + 3]);
    }
    ((float4*)y)[i] = o;
}

// ---------------- tf32 warp-MMA gather-GEMM conv ----------------
// CTA: 256 thr, M=128 x N=128; warp w: rows (w&3)*32, cols (w>>2)*64.
// K consumed in 32-wide chunks; SKIP adds 2 chunks of feats @ w_nin.
template <int CIN, bool SKIP>
__global__ void __launch_bounds__(256, 2)
k_conv(const float* __restrict__ src, const float* __restrict__ wt,
       const float* __restrict__ fsrc, const float* __restrict__ wnt,
       float* __restrict__ dst) {
    extern __shared__ __align__(16) char smraw[];
    // [0, 65536): 2 stages x (A 16KB | B 16KB); [65536, +13824): gather indices
    int* sIdx = (int*)(smraw + 65536);
    const uint32_t tile0 = smem_u32(smraw);

    const int tid  = threadIdx.x;
    const int lane = tid & 31;
    const int wid  = tid >> 5;
    const int g    = lane >> 2;      // quad id
    const int tig  = lane & 3;       // thread-in-group
    const int row0 = blockIdx.x * 128;
    const int warpRow = (wid & 3) * 32;
    const int warpCol = (wid >> 2) * 64;

    constexpr int CPK = CIN / 32;
    constexpr int CHM = KOFF * CPK;
    constexpr int CH  = SKIP ? CHM + 2 : CHM;

    // preload gather indices for this tile
    for (int i = tid; i < KOFF * 128; i += 256) {
        int k = i >> 7, r = i & 127;
        int row = row0 + r;
        sIdx[i] = (row < NV) ? g_g2[k * NV + row] : NV;
    }
    __syncthreads();

    auto issue = [&](int s) {
        const uint32_t aB = tile0 + (uint32_t)(s & 1) * 32768u;
        const uint32_t bB = aB + 16384u;
        if (!SKIP || s < CHM) {
            const int k27 = s / CPK;
            const int kb  = (s % CPK) * 32;
            const float* abase = src + kb;
            #pragma unroll
            for (int j = 0; j < 4; ++j) {
                int idx = tid + j * 256;
                int r = idx >> 3, sub = idx & 7;
                int gg = sIdx[(k27 << 7) + r];
                cpa16(aB + (uint32_t)((r << 7) + ((sub ^ (r & 7)) << 4)),
                      abase + (size_t)gg * CIN + sub * 4);
            }
            const float* bbase = wt + ((size_t)k27 * 128) * CIN + kb;
            #pragma unroll
            for (int j = 0; j < 4; ++j) {
                int idx = tid + j * 256;
                int n = idx >> 3, sub = idx & 7;
                cpa16(bB + (uint32_t)((n << 7) + ((sub ^ (n & 7)) << 4)),
                      bbase + (size_t)n * CIN + sub * 4);
            }
        } else {
            const int kb = (s - CHM) * 32;
            #pragma unroll
            for (int j = 0; j < 4; ++j) {
                int idx = tid + j * 256;
                int r = idx >> 3, sub = idx & 7;
                int row = row0 + r;
                int rc = row < NV ? row : NV - 1;
                cpa16z(aB + (uint32_t)((r << 7) + ((sub ^ (r & 7)) << 4)),
                       fsrc + (size_t)rc * CA + kb + sub * 4,
                       row < NV ? 16 : 0);
            }
            #pragma unroll
            for (int j = 0; j < 4; ++j) {
                int idx = tid + j * 256;
                int n = idx >> 3, sub = idx & 7;
                cpa16(bB + (uint32_t)((n << 7) + ((sub ^ (n & 7)) << 4)),
                      wnt + (size_t)n * CA + kb + sub * 4);
            }
        }
        cpa_commit();
    };

    float acc[2][8][4];
    #pragma unroll
    for (int mt = 0; mt < 2; ++mt)
        #pragma unroll
        for (int nt = 0; nt < 8; ++nt)
            #pragma unroll
            for (int q = 0; q < 4; ++q) acc[mt][nt][q] = 0.f;

    issue(0);

    for (int s = 0; s < CH; ++s) {
        if (s + 1 < CH) { issue(s + 1); cpa_wait1(); }
        else            { cpa_wait0(); }
        __syncthreads();

        const char* aB = smraw + (s & 1) * 32768;
        const char* bB = aB + 16384;
        const uint32_t sw = (uint32_t)(g << 4);   // swizzle term (bytes)

        #pragma unroll
        for (int kk = 0; kk < 32; kk += 8) {
            const uint32_t c0 = ((uint32_t)((kk + tig) << 2)) ^ sw;        // bytes
            const uint32_t c1 = ((uint32_t)((kk + tig + 4) << 2)) ^ sw;
            uint32_t a[2][4];
            #pragma unroll
            for (int mt = 0; mt < 2; ++mt) {
                int r = warpRow + mt * 16 + g;
                const char* pr0 = aB + (r << 7);
                const char* pr1 = aB + ((r + 8) << 7);
                a[mt][0] = *(const uint32_t*)(pr0 + c0);
                a[mt][1] = *(const uint32_t*)(pr1 + c0);
                a[mt][2] = *(const uint32_t*)(pr0 + c1);
                a[mt][3] = *(const uint32_t*)(pr1 + c1);
            }
            #pragma unroll
            for (int nt = 0; nt < 8; ++nt) {
                int n = warpCol + nt * 8 + g;
                uint32_t b[2];
                b[0] = *(const uint32_t*)(bB + (n << 7) + c0);
                b[1] = *(const uint32_t*)(bB + (n << 7) + c1);
                mma8(acc[0][nt], a[0], b);
                mma8(acc[1][nt], a[1], b);
            }
        }
        __syncthreads();
    }

    // epilogue: direct register -> gmem
    #pragma unroll
    for (int mt = 0; mt < 2; ++mt) {
        int r0r = row0 + warpRow + mt * 16 + g;
        #pragma unroll
        for (int nt = 0; nt < 8; ++nt) {
            int col = warpCol + nt * 8 + 2 * tig;
            if (r0r < NV)
                *(float2*)(dst + (size_t)r0r * CB + col) =
                    make_float2(acc[mt][nt][0], acc[mt][nt][1]);
            if (r0r + 8 < NV)
                *(float2*)(dst + (size_t)(r0r + 8) * CB + col) =
                    make_float2(acc[mt][nt][2], acc[mt][nt][3]);
        }
    }
}

// ---------------- launch ----------------
extern "C" void kernel_launch(void* const* d_in, const int* in_sizes, int n_in,
                              void* d_out, int out_size) {
    const float* feats     = (const float*)d_in[0];
    const float* w1        = (const float*)d_in[1];
    const float* w2        = (const float*)d_in[2];
    const float* w_nin     = (const float*)d_in[3];
    const float* bn1_gamma = (const float*)d_in[4];
    const float* bn1_beta  = (const float*)d_in[5];
    const float* bn2_gamma = (const float*)d_in[6];
    const float* bn2_beta  = (const float*)d_in[7];
    const int*   gidx      = (const int*)d_in[8];
    const int*   sidx      = (const int*)d_in[9];
    float*       out       = (float*)d_out;

    const int dynsm = 65536 + KOFF * 128 * 4;   // tiles + index cache = 79360 B
    cudaFuncSetAttribute(k_conv<CA, false>, cudaFuncAttributeMaxDynamicSharedMemorySize, dynsm);
    cudaFuncSetAttribute(k_conv<CB, true >, cudaFuncAttributeMaxDynamicSharedMemorySize, dynsm);

    float *h0, *h1, *h1b, *f0, *w1t, *w2t, *wnt;
    cudaGetSymbolAddress((void**)&h0,  g_h0);
    cudaGetSymbolAddress((void**)&h1,  g_h1);
    cudaGetSymbolAddress((void**)&h1b, g_h1b);
    cudaGetSymbolAddress((void**)&f0,  g_f0);
    cudaGetSymbolAddress((void**)&w1t, g_w1t);
    cudaGetSymbolAddress((void**)&w2t, g_w2t);
    cudaGetSymbolAddress((void**)&wnt, g_wnt);

    const int mapN = KOFF * NV;
    k_init_g2 <<<(mapN + 255) / 256, 256>>>();
    k_build_g2<<<(mapN + 255) / 256, 256>>>(gidx, sidx);

    k_transpose<<<(KOFF * CA * 128 + 255) / 256, 256>>>(w1, w1t, KOFF, CA);
    k_transpose<<<(KOFF * CB * 128 + 255) / 256, 256>>>(w2, w2t, KOFF, CB);
    k_transpose<<<(CA * 128 + 255) / 256, 256>>>(w_nin, wnt, 1, CA);
    k_round<<<(NV * CA + 255) / 256, 256>>>(feats, f0, NV * CA);

    k_bn_partial<CA> <<<NBLK, 256>>>(feats);
    k_bn_finalize<CA, 0><<<1, 4 * CA>>>(bn1_gamma, bn1_beta);
    {
        int n4 = (NV + 1) * CA / 4;
        k_bn_apply<CA, 0><<<(n4 + 255) / 256, 256>>>(feats, h0);
    }

    const int grid = (NV + 127) / 128;
    k_conv<CA, false><<<grid, 256, dynsm>>>(h0, w1t, nullptr, nullptr, h1);

    k_bn_partial<CB> <<<NBLK, 256>>>(h1);
    k_bn_finalize<CB, 1><<<1, 4 * CB>>>(bn2_gamma, bn2_beta);
    {
        int n4 = (NV + 1) * CB / 4;
        k_bn_apply<CB, 1><<<(n4 + 255) / 256, 256>>>(h1, h1b);
    }

    k_conv<CB, true><<<grid, 256, dynsm>>>(h1b, w2t, f0, wnt, out);
}

// round 4
// speedup vs baseline: 6.0024x; 1.4340x over previous
#include <cuda_runtime.h>
#include <cuda_fp16.h>
#include <cstdint>

#define NV   200000
#define KOFF 27
#define CA   64
#define CB   128
#define NBLK 256
#define EPSF 1e-5f

// ---------------- device scratch ----------------
__device__ __half g_f0h[(NV + 1) * CA];      // fp16(feats), zero dummy row
__device__ __half g_h1h[(NV + 1) * CB];      // fp16 conv1 out, zero dummy row
__device__ int    g_g2 [KOFF * NV];          // inverse map, stores gidx+1 (0 = invalid)
__device__ __half g_w1h[KOFF * CB * CA];     // fp16( bn1_scale[c] * w1[k][c][n] ) as [k][n][c]
__device__ __half g_w2h[KOFF * CB * CB];     // fp16( bn2_scale[c] * w2[k][c][n] ) as [k][n][c]
__device__ __half g_tb1[CB * 64];            // bias-trick B for conv1: [n][kk], kk<27 used
__device__ __half g_tb2[CB * 64];            // bias-trick B for conv2
__device__ __half g_wnh[CB * 64];            // fp16(w_nin) as [n][c]
__device__ float  g_psum[NBLK * CB];
__device__ float  g_psq [NBLK * CB];
__device__ float  g_sc[2][CB];
__device__ float  g_sh[2][CB];

// ---------------- helpers ----------------
__device__ __forceinline__ uint32_t smem_u32(const void* p) {
    uint32_t a;
    asm("{ .reg .u64 t; cvta.to.shared.u64 t, %1; cvt.u32.u64 %0, t; }" : "=r"(a) : "l"(p));
    return a;
}
__device__ __forceinline__ void cpa16(uint32_t s, const void* g) {
    asm volatile("cp.async.cg.shared.global [%0], [%1], 16;" :: "r"(s), "l"(g));
}
__device__ __forceinline__ void cpa_commit() {
    asm volatile("cp.async.commit_group;" ::: "memory");
}
__device__ __forceinline__ void cpa_wait2() { asm volatile("cp.async.wait_group 2;" ::: "memory"); }
__device__ __forceinline__ void cpa_wait1() { asm volatile("cp.async.wait_group 1;" ::: "memory"); }
__device__ __forceinline__ void cpa_wait0() { asm volatile("cp.async.wait_group 0;" ::: "memory"); }
__device__ __forceinline__ void sts16(uint32_t addr, uint4 v) {
    asm volatile("st.shared.v4.b32 [%0], {%1,%2,%3,%4};"
                 :: "r"(addr), "r"(v.x), "r"(v.y), "r"(v.z), "r"(v.w) : "memory");
}
__device__ __forceinline__ void ldsm4(uint32_t* d, uint32_t addr) {
    asm volatile("ldmatrix.sync.aligned.m8n8.x4.shared.b16 {%0,%1,%2,%3}, [%4];"
                 : "=r"(d[0]), "=r"(d[1]), "=r"(d[2]), "=r"(d[3]) : "r"(addr));
}
__device__ __forceinline__ void mma16(float* c, const uint32_t* a, const uint32_t* b) {
    asm volatile(
        "mma.sync.aligned.m16n8k16.row.col.f32.f16.f16.f32 "
        "{%0,%1,%2,%3}, {%4,%5,%6,%7}, {%8,%9}, {%0,%1,%2,%3};"
        : "+f"(c[0]), "+f"(c[1]), "+f"(c[2]), "+f"(c[3])
        : "r"(a[0]), "r"(a[1]), "r"(a[2]), "r"(a[3]), "r"(b[0]), "r"(b[1]));
}

// ---------------- BN stats: fp32 input (feats) ----------------
template <int C>
__global__ void k_bn_partial(const float* __restrict__ x) {
    const int C4 = C / 4;
    float4 s = make_float4(0.f, 0.f, 0.f, 0.f);
    float4 q = make_float4(0.f, 0.f, 0.f, 0.f);
    const int tot = NV * C4;
    const int tid = threadIdx.x;
    for (int i = blockIdx.x * 256 + tid; i < tot; i += NBLK * 256) {
        float4 v = ((const float4*)x)[i];
        s.x += v.x; s.y += v.y; s.z += v.z; s.w += v.w;
        q.x += v.x * v.x; q.y += v.y * v.y; q.z += v.z * v.z; q.w += v.w * v.w;
    }
    __shared__ float4 sh[256];
    sh[tid] = s;
    __syncthreads();
    if (tid < C4) {
        float4 a = sh[tid];
        for (int o = C4; o < 256; o += C4) {
            float4 b = sh[tid + o];
            a.x += b.x; a.y += b.y; a.z += b.z; a.w += b.w;
        }
        ((float4*)(g_psum + blockIdx.x * C))[tid] = a;
    }
    __syncthreads();
    sh[tid] = q;
    __syncthreads();
    if (tid < C4) {
        float4 a = sh[tid];
        for (int o = C4; o < 256; o += C4) {
            float4 b = sh[tid + o];
            a.x += b.x; a.y += b.y; a.z += b.z; a.w += b.w;
        }
        ((float4*)(g_psq + blockIdx.x * C))[tid] = a;
    }
}

// ---------------- BN stats: fp16 input (h1h), C = 128 ----------------
__global__ void k_bn_partial_h(const __half* __restrict__ x) {
    // each uint4 = 8 halfs; channel base = (i % 16) * 8, constant per thread
    float s[8], q[8];
    #pragma unroll
    for (int t = 0; t < 8; ++t) { s[t] = 0.f; q[t] = 0.f; }
    const int tid = threadIdx.x;
    const int tot = NV * 16;   // uint4 count
    for (int i = blockIdx.x * 256 + tid; i < tot; i += NBLK * 256) {
        uint4 v = ((const uint4*)x)[i];
        const uint32_t u[4] = {v.x, v.y, v.z, v.w};
        #pragma unroll
        for (int p = 0; p < 4; ++p) {
            float2 f = __half22float2(*(const __half2*)&u[p]);
            s[2 * p] += f.x; s[2 * p + 1] += f.y;
            q[2 * p] += f.x * f.x; q[2 * p + 1] += f.y * f.y;
        }
    }
    __shared__ float sh[256 * 8];
    #pragma unroll
    for (int t = 0; t < 8; ++t) sh[tid * 8 + t] = s[t];
    __syncthreads();
    if (tid < 128) {
        int cb = tid >> 3, ci = tid & 7;   // channel = cb*8+ci, owner threads: cb + 16*j
        float a = 0.f;
        #pragma unroll
        for (int j = 0; j < 16; ++j) a += sh[(cb + 16 * j) * 8 + ci];
        g_psum[blockIdx.x * 128 + tid] = a;
    }
    __syncthreads();
    #pragma unroll
    for (int t = 0; t < 8; ++t) sh[tid * 8 + t] = q[t];
    __syncthreads();
    if (tid < 128) {
        int cb = tid >> 3, ci = tid & 7;
        float a = 0.f;
        #pragma unroll
        for (int j = 0; j < 16; ++j) a += sh[(cb + 16 * j) * 8 + ci];
        g_psq[blockIdx.x * 128 + tid] = a;
    }
}

template <int C, int IDX>
__global__ void k_bn_finalize(const float* __restrict__ gamma, const float* __restrict__ beta) {
    const int tid = threadIdx.x;   // blockDim = 4*C
    const int c = tid % C;
    const int qd = tid / C;
    float s = 0.f, s2 = 0.f;
    #pragma unroll 8
    for (int b = qd * (NBLK / 4); b < (qd + 1) * (NBLK / 4); ++b) {
        s  += g_psum[b * C + c];
        s2 += g_psq [b * C + c];
    }
    __shared__ float sha[4 * CB], shb[4 * CB];
    sha[tid] = s; shb[tid] = s2;
    __syncthreads();
    if (qd == 0) {
        s  = sha[c] + sha[C + c] + sha[2 * C + c] + sha[3 * C + c];
        s2 = shb[c] + shb[C + c] + shb[2 * C + c] + shb[3 * C + c];
        float mean = s / (float)NV;
        float var  = s2 / (float)NV - mean * mean;
        float a = rsqrtf(var + EPSF) * gamma[c];
        g_sc[IDX][c] = a;
        g_sh[IDX][c] = beta[c] - mean * a;
    }
}

// ---------------- prep1: f0h convert + w1 fold + tb1 + dummy rows + map -----
#define NB_F0  12500          // NV*64/4/256
#define NB_W1  864            // 27*128*64/256
#define NB_TB  32             // 128*64/256
#define NB_MI  1
#define NB_MAP 21094          // ceil(27*NV/256)
__global__ void k_prep1(const float* __restrict__ feats, const float* __restrict__ w1,
                        const int* __restrict__ gidx, const int* __restrict__ sidx) {
    const int b = blockIdx.x;
    const int tid = threadIdx.x;
    if (b < NB_F0) {
        int i = b * 256 + tid;                 // float4 index, 3.2M total
        float4 v = ((const float4*)feats)[i];
        ((__half2*)g_f0h)[2 * i]     = __floats2half2_rn(v.x, v.y);
        ((__half2*)g_f0h)[2 * i + 1] = __floats2half2_rn(v.z, v.w);
    } else if (b < NB_F0 + NB_W1) {
        int i = (b - NB_F0) * 256 + tid;       // 221184
        int k = i >> 13;                       // /8192
        int rem = i & 8191;
        int n = rem >> 6, c = rem & 63;
        g_w1h[i] = __float2half_rn(g_sc[0][c] * w1[(k * 64 + c) * 128 + n]);
    } else if (b < NB_F0 + NB_W1 + NB_TB) {
        int i = (b - NB_F0 - NB_W1) * 256 + tid;  // 8192
        int n = i >> 6, kk = i & 63;
        float acc = 0.f;
        if (kk < KOFF)
            for (int c = 0; c < 64; ++c)
                acc += g_sh[0][c] * w1[(kk * 64 + c) * 128 + n];
        g_tb1[i] = __float2half_rn(acc);
    } else if (b < NB_F0 + NB_W1 + NB_TB + NB_MI) {
        if (tid < 32)                ((__half2*)(g_f0h + NV * CA))[tid] = __half2half2(__ushort_as_half(0));
        if (tid >= 32 && tid < 96)   ((__half2*)(g_h1h + NV * CB))[tid - 32] = __half2half2(__ushort_as_half(0));
    } else {
        int j = (b - NB_F0 - NB_W1 - NB_TB - NB_MI) * 256 + tid;
        if (j < KOFF * NV) {
            int s = sidx[j];
            if (s < NV) {
                int k = j / NV;
                g_g2[k * NV + s] = gidx[j] + 1;
            }
        }
    }
}

// ---------------- prep2: w2 fold + tb2 + w_nin ----------------
#define NB_W2  1728           // 27*128*128/256
__global__ void k_prep2(const float* __restrict__ w2, const float* __restrict__ wnin) {
    const int b = blockIdx.x;
    const int tid = threadIdx.x;
    if (b < NB_W2) {
        int i = b * 256 + tid;                 // 442368
        int k = i >> 14;                       // /16384
        int rem = i & 16383;
        int n = rem >> 7, c = rem & 127;
        g_w2h[i] = __float2half_rn(g_sc[1][c] * w2[(k * 128 + c) * 128 + n]);
    } else if (b < NB_W2 + NB_TB) {
        int i = (b - NB_W2) * 256 + tid;
        int n = i >> 6, kk = i & 63;
        float acc = 0.f;
        if (kk < KOFF)
            for (int c = 0; c < 128; ++c)
                acc += g_sh[1][c] * w2[(kk * 128 + c) * 128 + n];
        g_tb2[i] = __float2half_rn(acc);
    } else {
        int i = (b - NB_W2 - NB_TB) * 256 + tid;  // 8192
        int n = i >> 6, c = i & 63;
        g_wnh[i] = __float2half_rn(wnin[c * 128 + n]);
    }
}

// ---------------- fp16 warp-MMA gather-GEMM conv ----------------
// CTA: 256 thr, tile M=128 x N=128; warp: rows (wid&3)*32, cols (wid>>2)*64.
// K chunks of 64; 3-stage cp.async pipeline.
// Chunks: MAIN gather chunks (+ skip identity chunk if SKIP) + 1 bias-mask chunk.
template <int CIN, bool SKIP, bool OUTH>
__global__ void __launch_bounds__(256, 2)
k_conv(const __half* __restrict__ src, const __half* __restrict__ wt,
       const __half* __restrict__ tb, void* __restrict__ dstv) {
    extern __shared__ __align__(16) char smraw[];
    int* sIdx = (int*)(smraw + 3 * 32768);
    const uint32_t tile0 = smem_u32(smraw);

    const int tid  = threadIdx.x;
    const int lane = tid & 31;
    const int wid  = tid >> 5;
    const int g    = lane >> 2;
    const int tig  = lane & 3;
    const int row0 = blockIdx.x * 128;
    const int warpRow = (wid & 3) * 32;
    const int warpCol = (wid >> 2) * 64;

    constexpr int CPK  = CIN / 64;
    constexpr int MAIN = KOFF * CPK;
    constexpr int CH   = MAIN + (SKIP ? 1 : 0) + 1;

    for (int i = tid; i < KOFF * 128; i += 256) {
        int k = i >> 7, r = i & 127;
        int row = row0 + r;
        int v = (row < NV) ? g_g2[k * NV + row] : 0;
        sIdx[i] = v ? (v - 1) : NV;
    }
    __syncthreads();

    const int lr  = tid >> 3;     // 0..31 row group for loads
    const int sub = tid & 7;      // 16B unit within row

    auto issue = [&](int s) {
        const uint32_t aB = tile0 + (uint32_t)(s % 3) * 32768u;
        const uint32_t bB = aB + 16384u;
        if (s < MAIN) {
            const int k27 = (CPK == 1) ? s : (s >> 1);
            const int kb  = (CPK == 1) ? 0 : ((s & 1) << 6);
            #pragma unroll
            for (int j = 0; j < 4; ++j) {
                int r = lr + j * 32;
                int gg = sIdx[(k27 << 7) + r];
                uint32_t off = (uint32_t)((r << 7) + ((sub ^ (r & 7)) << 4));
                cpa16(aB + off, src + (size_t)gg * CIN + kb + sub * 8);
            }
            const __half* bs = wt + ((size_t)k27 * 128) * CIN + kb;
            #pragma unroll
            for (int j = 0; j < 4; ++j) {
                int n = lr + j * 32;
                uint32_t off = (uint32_t)((n << 7) + ((sub ^ (n & 7)) << 4));
                cpa16(bB + off, bs + (size_t)n * CIN + sub * 8);
            }
        } else if (SKIP && s == MAIN) {
            #pragma unroll
            for (int j = 0; j < 4; ++j) {
                int r = lr + j * 32;
                int row = row0 + r;
                int gg = row < NV ? row : NV;
                uint32_t off = (uint32_t)((r << 7) + ((sub ^ (r & 7)) << 4));
                cpa16(aB + off, g_f0h + (size_t)gg * 64 + sub * 8);
            }
            #pragma unroll
            for (int j = 0; j < 4; ++j) {
                int n = lr + j * 32;
                uint32_t off = (uint32_t)((n << 7) + ((sub ^ (n & 7)) << 4));
                cpa16(bB + off, g_wnh + (size_t)n * 64 + sub * 8);
            }
        } else {
            // bias-mask chunk: A[r][kk] = (kk < 27 && gather valid) ? 1 : 0
            #pragma unroll
            for (int j = 0; j < 4; ++j) {
                int r = lr + j * 32;
                uint4 w;
                uint32_t* wp = (uint32_t*)&w;
                #pragma unroll
                for (int q = 0; q < 4; ++q) {
                    int kk0 = sub * 8 + 2 * q;
                    uint32_t h0 = (kk0 < KOFF && sIdx[(kk0 << 7) + r] != NV) ? 0x3C00u : 0u;
                    uint32_t h1 = (kk0 + 1 < KOFF && sIdx[((kk0 + 1) << 7) + r] != NV) ? 0x3C00u : 0u;
                    wp[q] = h0 | (h1 << 16);
                }
                uint32_t off = (uint32_t)((r << 7) + ((sub ^ (r & 7)) << 4));
                sts16(aB + off, w);
            }
            #pragma unroll
            for (int j = 0; j < 4; ++j) {
                int n = lr + j * 32;
                uint32_t off = (uint32_t)((n << 7) + ((sub ^ (n & 7)) << 4));
                cpa16(bB + off, tb + (size_t)n * 64 + sub * 8);
            }
        }
        cpa_commit();
    };

    float acc[2][8][4];
    #pragma unroll
    for (int mt = 0; mt < 2; ++mt)
        #pragma unroll
        for (int nt = 0; nt < 8; ++nt)
            #pragma unroll
            for (int q = 0; q < 4; ++q) acc[mt][nt][q] = 0.f;

    // per-thread ldmatrix address components
    const int s7 = lane & 7;
    const int rowA = warpRow + s7 + ((lane >> 3) & 1) * 8;
    const int uA   = lane >> 4;
    const int rowB = warpCol + s7 + (lane >> 4) * 8;
    const int uB   = (lane >> 3) & 1;

    issue(0);
    issue(1);

    for (int s = 0; s < CH; ++s) {
        if (s + 2 < CH)      { issue(s + 2); cpa_wait2(); }
        else if (s + 1 < CH) cpa_wait1();
        else                 cpa_wait0();
        __syncthreads();

        const uint32_t aB = tile0 + (uint32_t)(s % 3) * 32768u;
        const uint32_t bB = aB + 16384u;
        const uint32_t pa0 = aB + ((uint32_t)rowA << 7);
        const uint32_t pa1 = aB + ((uint32_t)(rowA + 16) << 7);

        #pragma unroll
        for (int ks = 0; ks < 4; ++ks) {
            const int u0 = ks * 2;
            uint32_t a[2][4];
            const uint32_t aoff = (uint32_t)(((u0 + uA) ^ s7) << 4);
            ldsm4(a[0], pa0 + aoff);
            ldsm4(a[1], pa1 + aoff);
            uint32_t bfr[4][4];
            const uint32_t boff = (uint32_t)(((u0 + uB) ^ s7) << 4);
            #pragma unroll
            for (int p = 0; p < 4; ++p)
                ldsm4(bfr[p], bB + ((uint32_t)(rowB + p * 16) << 7) + boff);
            #pragma unroll
            for (int p = 0; p < 4; ++p) {
                mma16(acc[0][2 * p],     a[0], &bfr[p][0]);
                mma16(acc[0][2 * p + 1], a[0], &bfr[p][2]);
                mma16(acc[1][2 * p],     a[1], &bfr[p][0]);
                mma16(acc[1][2 * p + 1], a[1], &bfr[p][2]);
            }
        }
        __syncthreads();
    }

    // epilogue
    #pragma unroll
    for (int mt = 0; mt < 2; ++mt) {
        int r0 = row0 + warpRow + mt * 16 + g;
        #pragma unroll
        for (int nt = 0; nt < 8; ++nt) {
            int col = warpCol + nt * 8 + 2 * tig;
            if (OUTH) {
                __half* dst = (__half*)dstv;
                if (r0 < NV)
                    *(__half2*)(dst + (size_t)r0 * CB + col) =
                        __floats2half2_rn(acc[mt][nt][0], acc[mt][nt][1]);
                if (r0 + 8 < NV)
                    *(__half2*)(dst + (size_t)(r0 + 8) * CB + col) =
                        __floats2half2_rn(acc[mt][nt][2], acc[mt][nt][3]);
            } else {
                float* dst = (float*)dstv;
                if (r0 < NV)
                    *(float2*)(dst + (size_t)r0 * CB + col) =
                        make_float2(acc[mt][nt][0], acc[mt][nt][1]);
                if (r0 + 8 < NV)
                    *(float2*)(dst + (size_t)(r0 + 8) * CB + col) =
                        make_float2(acc[mt][nt][2], acc[mt][nt][3]);
            }
        }
    }
}

// ---------------- launch ----------------
extern "C" void kernel_launch(void* const* d_in, const int* in_sizes, int n_in,
                              void* d_out, int out_size) {
    const float* feats     = (const float*)d_in[0];
    const float* w1        = (const float*)d_in[1];
    const float* w2        = (const float*)d_in[2];
    const float* w_nin     = (const float*)d_in[3];
    const float* bn1_gamma = (const float*)d_in[4];
    const float* bn1_beta  = (const float*)d_in[5];
    const float* bn2_gamma = (const float*)d_in[6];
    const float* bn2_beta  = (const float*)d_in[7];
    const int*   gidx      = (const int*)d_in[8];
    const int*   sidx      = (const int*)d_in[9];
    float*       out       = (float*)d_out;

    const int dynsm = 3 * 32768 + KOFF * 128 * 4;   // 112128 B
    cudaFuncSetAttribute(k_conv<CA, false, true >, cudaFuncAttributeMaxDynamicSharedMemorySize, dynsm);
    cudaFuncSetAttribute(k_conv<CB, true,  false>, cudaFuncAttributeMaxDynamicSharedMemorySize, dynsm);

    __half *f0h, *h1h, *w1h, *w2h, *tb1, *tb2;
    cudaGetSymbolAddress((void**)&f0h, g_f0h);
    cudaGetSymbolAddress((void**)&h1h, g_h1h);
    cudaGetSymbolAddress((void**)&w1h, g_w1h);
    cudaGetSymbolAddress((void**)&w2h, g_w2h);
    cudaGetSymbolAddress((void**)&tb1, g_tb1);
    cudaGetSymbolAddress((void**)&tb2, g_tb2);

    const int grid = (NV + 127) / 128;   // 1563

    // 1-2: BN1 stats
    k_bn_partial<CA><<<NBLK, 256>>>(feats);
    k_bn_finalize<CA, 0><<<1, 4 * CA>>>(bn1_gamma, bn1_beta);
    // 3: prep (feats->fp16, fold BN1 into w1, bias table, dummy rows, inverse map)
    k_prep1<<<NB_F0 + NB_W1 + NB_TB + NB_MI + NB_MAP, 256>>>(feats, w1, gidx, sidx);
    // 4: conv1 (profiled slot)
    k_conv<CA, false, true><<<grid, 256, dynsm>>>(f0h, w1h, tb1, h1h);
    // 5-6: BN2 stats on fp16 h1
    k_bn_partial_h<<<NBLK, 256>>>(h1h);
    k_bn_finalize<CB, 1><<<1, 4 * CB>>>(bn2_gamma, bn2_beta);
    // 7: prep2 (fold BN2 into w2, bias table, w_nin)
    k_prep2<<<NB_W2 + NB_TB + 32, 256>>>(w2, w_nin);
    // 8: conv2 + skip + bias
    k_conv<CB, true, false><<<grid, 256, dynsm>>>(h1h, w2h, tb2, out);
}